// round 6
// baseline (speedup 1.0000x reference)
#include <cuda_runtime.h>
#include <math.h>

#define N_COLS 4096
#define TPB    256
#define EPS    1e-14f

// Two rows per block, one barrier per TWO rows:
// out[r,i] = x[r,i] - (2*(x[r].v)/(||v||+eps)^2) * v[i] + bias[i]
// v is loaded once per block and dotted against both rows; both dot products
// and ||v||^2 share a single interleaved shuffle chain + single __syncthreads.
__global__ void __launch_bounds__(TPB, 4)
householder_kernel(const float* __restrict__ x,
                   const float* __restrict__ v,
                   const float* __restrict__ bias,
                   float* __restrict__ out) {
    const int tid = threadIdx.x;
    const int w = tid >> 5, l = tid & 31;
    const int row0 = blockIdx.x * 2;

    const float4* __restrict__ x0 = (const float4*)(x + (size_t)row0 * N_COLS);
    const float4* __restrict__ x1 = (const float4*)(x + (size_t)(row0 + 1) * N_COLS);
    const float4* __restrict__ vr = (const float4*)v;
    const float4* __restrict__ br = (const float4*)bias;
    float4* __restrict__ o0 = (float4*)(out + (size_t)row0 * N_COLS);
    float4* __restrict__ o1 = (float4*)(out + (size_t)(row0 + 1) * N_COLS);

    __shared__ float red0[TPB / 32];
    __shared__ float red1[TPB / 32];
    __shared__ float redn[TPB / 32];

    // ---- single pass: both rows + v, accumulate dot0, dot1, ||v||^2 ----
    float4 a[4], b[4];
    float d0 = 0.0f, d1 = 0.0f, vn = 0.0f;
    #pragma unroll
    for (int j = 0; j < 4; j++) {
        const int idx = tid + j * TPB;     // coalesced 128B per warp
        a[j] = x0[idx];
        b[j] = x1[idx];
        float4 t = vr[idx];                // L1/L2 broadcast-hot (16KB)
        d0 = fmaf(a[j].x, t.x, d0);  d1 = fmaf(b[j].x, t.x, d1);
        d0 = fmaf(a[j].y, t.y, d0);  d1 = fmaf(b[j].y, t.y, d1);
        d0 = fmaf(a[j].z, t.z, d0);  d1 = fmaf(b[j].z, t.z, d1);
        d0 = fmaf(a[j].w, t.w, d0);  d1 = fmaf(b[j].w, t.w, d1);
        vn = fmaf(t.x, t.x, vn);
        vn = fmaf(t.y, t.y, vn);
        vn = fmaf(t.z, t.z, vn);
        vn = fmaf(t.w, t.w, vn);
    }

    #pragma unroll
    for (int o = 16; o > 0; o >>= 1) {
        d0 += __shfl_xor_sync(0xffffffffu, d0, o);
        d1 += __shfl_xor_sync(0xffffffffu, d1, o);
        vn += __shfl_xor_sync(0xffffffffu, vn, o);
    }
    if (l == 0) { red0[w] = d0; red1[w] = d1; redn[w] = vn; }
    __syncthreads();                        // the ONLY barrier (per 2 rows)

    // every thread finishes the reductions itself (broadcast LDS)
    float t0 = 0.0f, t1 = 0.0f, tn = 0.0f;
    #pragma unroll
    for (int i = 0; i < TPB / 32; i++) {
        t0 += red0[i]; t1 += red1[i]; tn += redn[i];
    }
    const float s = 1.0f / (sqrtf(tn) + EPS);
    const float s2 = 2.0f * s * s;
    const float c0 = t0 * s2;
    const float c1 = t1 * s2;

    // ---- epilogue: reload v (L1-hot) + bias once, apply to both rows ----
    #pragma unroll
    for (int j = 0; j < 4; j++) {
        const int idx = tid + j * TPB;
        float4 vv = vr[idx];
        float4 bb = br[idx];
        float4 r0, r1;
        r0.x = fmaf(-c0, vv.x, a[j].x) + bb.x;
        r0.y = fmaf(-c0, vv.y, a[j].y) + bb.y;
        r0.z = fmaf(-c0, vv.z, a[j].z) + bb.z;
        r0.w = fmaf(-c0, vv.w, a[j].w) + bb.w;
        r1.x = fmaf(-c1, vv.x, b[j].x) + bb.x;
        r1.y = fmaf(-c1, vv.y, b[j].y) + bb.y;
        r1.z = fmaf(-c1, vv.z, b[j].z) + bb.z;
        r1.w = fmaf(-c1, vv.w, b[j].w) + bb.w;
        o0[idx] = r0;
        o1[idx] = r1;
    }
}

extern "C" void kernel_launch(void* const* d_in, const int* in_sizes, int n_in,
                              void* d_out, int out_size) {
    const float* x    = (const float*)d_in[0];   // [16384, 4096]
    const float* v    = (const float*)d_in[1];   // [4096, 1]
    const float* bias = (const float*)d_in[2];   // [4096]
    float* out = (float*)d_out;

    const int n_rows = in_sizes[0] / N_COLS;     // 16384 (even)

    householder_kernel<<<n_rows / 2, TPB>>>(x, v, bias, out);
}